// round 16
// baseline (speedup 1.0000x reference)
#include <cuda_runtime.h>
#include <cuda_bf16.h>

// Problem constants (fixed shapes from reference)
#define B_     128
#define C_     1024
#define HW_    196          // 14*14
#define VEC_   49           // 196/4 float4 per channel row
#define CHUNKS 8            // 8*128 = 1024 blocks -> single wave on 148 SMs
#define CPB    128          // channels per block
#define THREADS 256         // 8 warps
#define NPART  (B_*CHUNKS)  // 1024 partials (one per block)

#define MARGIN 1.0f
#define EPS    1e-6f

__device__ float g_partials[NPART];
__device__ unsigned int g_ticket = 0;   // self-resetting; replay-safe

__device__ __forceinline__ void cp16(void* smem_dst, const void* gmem_src) {
    unsigned saddr = (unsigned)__cvta_generic_to_shared(smem_dst);
    asm volatile("cp.async.cg.shared.global [%0], [%1], 16;\n"
                 :: "r"(saddr), "l"(gmem_src));
}

// smem-limited to 8 blocks/SM (25KB buffers); reg cap 32 keeps 64 warps/SM.
__global__ __launch_bounds__(THREADS, 8)
void ffl_fused_kernel(const float* __restrict__ feat,
                      const float* __restrict__ feat_p,
                      const float* __restrict__ avg_feat,   // [2,1024]
                      const int* __restrict__ qual,         // [128] int32
                      const int* __restrict__ label,        // [128] int32
                      float* __restrict__ out)
{
    const int chunk = blockIdx.x;        // 0..7
    const int b     = blockIdx.y;        // 0..127
    const int tid   = threadIdx.x;
    const int warp  = tid >> 5;          // 0..7
    const int lane  = tid & 31;

    // Double-buffered per-warp staging: [stage][warp][ch][vec]
    __shared__ float4 buf[2][8][2][VEC_];    // 25088 B
    __shared__ float  warp_acc[8];
    __shared__ bool   is_last;

    // Select source tensor for this sample (only this one is read)
    const int q  = qual[b];
    const float* __restrict__ src = (q == 1) ? feat : feat_p;
    const int lb = label[b] & 1;   // mask: guaranteed in-bounds gather
    const float* __restrict__ af_pos = avg_feat + (size_t)lb * C_;
    const float* __restrict__ af_neg = avg_feat + (size_t)(1 - lb) * C_;

    // This warp owns 16 contiguous channels: cbase .. cbase+15
    const int cbase = chunk * CPB + warp * 16;
    const float4* __restrict__ base =
        reinterpret_cast<const float4*>(src + ((size_t)b * C_ + cbase) * HW_);

    const bool tail = (lane < VEC_ - 32);   // lanes 0..16 handle the second vec

    // Issue one 2-channel chunk (iteration 'it') into stage p, fire-and-forget.
    #define ISSUE(it, p)                                                      \
        do {                                                                  \
            const float4* gA = base + (size_t)(2 * (it))     * VEC_;          \
            const float4* gB = base + (size_t)(2 * (it) + 1) * VEC_;          \
            cp16(&buf[p][warp][0][lane], gA + lane);                          \
            cp16(&buf[p][warp][1][lane], gB + lane);                          \
            if (tail) {                                                       \
                cp16(&buf[p][warp][0][lane + 32], gA + lane + 32);            \
                cp16(&buf[p][warp][1][lane + 32], gB + lane + 32);            \
            }                                                                 \
            asm volatile("cp.async.commit_group;\n" ::: "memory");            \
        } while (0)

    ISSUE(0, 0);
    ISSUE(1, 1);

    float acc = 0.0f;

    #pragma unroll
    for (int it = 0; it < 8; ++it) {
        const int p = it & 1;
        if (it < 7) asm volatile("cp.async.wait_group 1;\n" ::: "memory");
        else        asm volatile("cp.async.wait_group 0;\n" ::: "memory");
        __syncwarp();

        // Reduce this chunk's 2 channels from SMEM (off the stream's path).
        float4 a0 = buf[p][warp][0][lane];
        float4 b0 = buf[p][warp][1][lane];
        float sA = (a0.x + a0.y) + (a0.z + a0.w);
        float sB = (b0.x + b0.y) + (b0.z + b0.w);
        if (tail) {
            float4 a1 = buf[p][warp][0][lane + 32];
            float4 b1 = buf[p][warp][1][lane + 32];
            sA += (a1.x + a1.y) + (a1.z + a1.w);
            sB += (b1.x + b1.y) + (b1.z + b1.w);
        }
        __syncwarp();
        // Refill freed stage immediately so the stream never drains.
        if (it + 2 < 8) ISSUE(it + 2, p);

        #pragma unroll
        for (int off = 16; off > 0; off >>= 1) {
            sA += __shfl_xor_sync(0xFFFFFFFFu, sA, off);
            sB += __shfl_xor_sync(0xFFFFFFFFu, sB, off);
        }
        if (lane == 0) {
            const int   c0   = cbase + 2 * it;
            const int   c1   = c0 + 1;
            const float selA = sA * (1.0f / (float)HW_);
            const float selB = sB * (1.0f / (float)HW_);
            acc += fmaxf(fabsf(selA - af_pos[c0] + EPS) - fabsf(selA - af_neg[c0] + EPS) + MARGIN, 0.0f);
            acc += fmaxf(fabsf(selB - af_pos[c1] + EPS) - fabsf(selB - af_neg[c1] + EPS) + MARGIN, 0.0f);
        }
    }
    #undef ISSUE

    // Block reduce the 8 warp-leader partials (fixed order -> deterministic)
    if (lane == 0) warp_acc[warp] = acc;
    __syncthreads();
    if (tid == 0) {
        float t = 0.0f;
        #pragma unroll
        for (int w = 0; w < 8; ++w) t += warp_acc[w];
        __stcg(&g_partials[b * CHUNKS + chunk], t * (1.0f / (float)C_));
        __threadfence();
        unsigned int ticket = atomicAdd(&g_ticket, 1u);
        is_last = (ticket == NPART - 1);
    }
    __syncthreads();

    // Last block to finish performs the deterministic final sum.
    if (is_last) {
        if (tid == 0) g_ticket = 0;   // reset for next graph replay
        float s2 = 0.0f;
        #pragma unroll
        for (int i = 0; i < NPART / THREADS; ++i)       // 4 each, fixed order
            s2 += __ldcg(&g_partials[tid + i * THREADS]);

        __shared__ float sm[THREADS];
        sm[tid] = s2;
        __syncthreads();
        #pragma unroll
        for (int step = THREADS / 2; step > 0; step >>= 1) {
            if (tid < step) sm[tid] += sm[tid + step];
            __syncthreads();
        }
        if (tid == 0) out[0] = sm[0];
    }
}

extern "C" void kernel_launch(void* const* d_in, const int* in_sizes, int n_in,
                              void* d_out, int out_size)
{
    const float* feat     = (const float*)d_in[0];
    const float* feat_p   = (const float*)d_in[1];
    const float* avg_feat = (const float*)d_in[2];
    const int*   qual     = (const int*)d_in[3];
    const int*   label    = (const int*)d_in[4];
    float* out = (float*)d_out;

    dim3 grid(CHUNKS, B_);
    ffl_fused_kernel<<<grid, THREADS>>>(feat, feat_p, avg_feat, qual, label, out);
}

// round 17
// speedup vs baseline: 1.1175x; 1.1175x over previous
#include <cuda_runtime.h>
#include <cuda_bf16.h>

// Problem constants (fixed shapes from reference)
#define B_     128
#define C_     1024
#define HW_    196          // 14*14
#define VEC_   49           // 196/4 float4 per channel row
#define CHUNKS 8            // 8*128 = 1024 blocks -> single wave on 148 SMs
#define CPB    128          // channels per block
#define THREADS 256         // 8 warps
#define NPART  (B_*CHUNKS)  // 1024 partials (one per block)

#define MARGIN 1.0f
#define EPS    1e-6f

__device__ float g_partials[NPART];
__device__ unsigned int g_ticket = 0;   // self-resetting; replay-safe

// minBlocks=7 -> reg cap 36 (grid is 6.92 blocks/SM, so 7-resident is still a
// single wave) -> slightly deeper load pipelining than the 32-reg point.
__global__ __launch_bounds__(THREADS, 7)
void ffl_fused_kernel(const float* __restrict__ feat,
                      const float* __restrict__ feat_p,
                      const float* __restrict__ avg_feat,   // [2,1024]
                      const int* __restrict__ qual,         // [128] int32
                      const int* __restrict__ label,        // [128] int32
                      float* __restrict__ out)
{
    const int chunk = blockIdx.x;        // 0..7
    const int b     = blockIdx.y;        // 0..127
    const int tid   = threadIdx.x;
    const int warp  = tid >> 5;          // 0..7
    const int lane  = tid & 31;

    // Per-lane channel partials: [warp][channel-in-warp][lane]
    __shared__ float sm_part[8][16][32];     // 16 KB
    __shared__ float sm_red[CPB];            // per-channel losses
    __shared__ bool  is_last;

    // Select source tensor for this sample (only this one is read)
    const int q  = qual[b];
    const float* __restrict__ src = (q == 1) ? feat : feat_p;
    const int lb = label[b] & 1;   // mask: guaranteed in-bounds gather
    const float* __restrict__ af_pos = avg_feat + (size_t)lb * C_;
    const float* __restrict__ af_neg = avg_feat + (size_t)(1 - lb) * C_;

    // This warp owns 16 contiguous channels: cbase .. cbase+15
    const int cbase = chunk * CPB + warp * 16;
    const float4* __restrict__ base =
        reinterpret_cast<const float4*>(src + ((size_t)b * C_ + cbase) * HW_);

    const bool tail = (lane < VEC_ - 32);   // lanes 0..16 load the second vec

    // ---- Streaming loop: pure LDG -> FADD -> STS, no cross-lane deps ----
    #pragma unroll
    for (int it = 0; it < 8; ++it) {
        const float4* __restrict__ rowA = base + (size_t)(2 * it)     * VEC_;
        const float4* __restrict__ rowB = base + (size_t)(2 * it + 1) * VEC_;

        float4 a0 = rowA[lane];
        float4 b0 = rowB[lane];
        float4 a1, b1;
        if (tail) { a1 = rowA[lane + 32]; b1 = rowB[lane + 32]; }

        float sA = (a0.x + a0.y) + (a0.z + a0.w);
        float sB = (b0.x + b0.y) + (b0.z + b0.w);
        if (tail) {
            sA += (a1.x + a1.y) + (a1.z + a1.w);
            sB += (b1.x + b1.y) + (b1.z + b1.w);
        }
        sm_part[warp][2 * it][lane]     = sA;
        sm_part[warp][2 * it + 1][lane] = sB;
    }
    __syncthreads();

    // ---- Deferred reduction: thread c sums channel c's 32 lane-partials ----
    // Lane-rotated, conflict-free LDS; 4 split accumulators break the serial
    // FADD chain (32*4cyc -> ~8*4cyc critical path).
    if (tid < CPB) {
        const int w = tid >> 4;
        const int r = tid & 15;
        const int rot = tid & 31;
        float s0 = 0.f, s1 = 0.f, s2 = 0.f, s3 = 0.f;
        #pragma unroll
        for (int j = 0; j < 32; j += 4) {
            s0 += sm_part[w][r][(j + 0 + rot) & 31];
            s1 += sm_part[w][r][(j + 1 + rot) & 31];
            s2 += sm_part[w][r][(j + 2 + rot) & 31];
            s3 += sm_part[w][r][(j + 3 + rot) & 31];
        }
        const float sum = (s0 + s1) + (s2 + s3);

        const int   c   = chunk * CPB + tid;    // global channel
        const float sel = sum * (1.0f / (float)HW_);
        sm_red[tid] = fmaxf(fabsf(sel - af_pos[c] + EPS)
                          - fabsf(sel - af_neg[c] + EPS) + MARGIN, 0.0f);
    }
    __syncthreads();

    // ---- Warp 0 reduces the 128 channel losses (fixed order, 1 warp) ----
    if (warp == 0) {
        float t = (sm_red[lane]      + sm_red[lane + 32])
                + (sm_red[lane + 64] + sm_red[lane + 96]);
        #pragma unroll
        for (int off = 16; off > 0; off >>= 1)
            t += __shfl_xor_sync(0xFFFFFFFFu, t, off);

        if (lane == 0) {
            __stcg(&g_partials[b * CHUNKS + chunk], t * (1.0f / (float)C_));
            __threadfence();
            unsigned int ticket = atomicAdd(&g_ticket, 1u);
            is_last = (ticket == NPART - 1);
        }
    }
    __syncthreads();

    // Last block to finish performs the deterministic final sum.
    if (is_last) {
        if (tid == 0) g_ticket = 0;   // reset for next graph replay
        float s2 = 0.0f;
        #pragma unroll
        for (int i = 0; i < NPART / THREADS; ++i)       // 4 each, fixed order
            s2 += __ldcg(&g_partials[tid + i * THREADS]);

        __shared__ float sm[THREADS];
        sm[tid] = s2;
        __syncthreads();
        #pragma unroll
        for (int step = THREADS / 2; step > 0; step >>= 1) {
            if (tid < step) sm[tid] += sm[tid + step];
            __syncthreads();
        }
        if (tid == 0) out[0] = sm[0];
    }
}

extern "C" void kernel_launch(void* const* d_in, const int* in_sizes, int n_in,
                              void* d_out, int out_size)
{
    const float* feat     = (const float*)d_in[0];
    const float* feat_p   = (const float*)d_in[1];
    const float* avg_feat = (const float*)d_in[2];
    const int*   qual     = (const int*)d_in[3];
    const int*   label    = (const int*)d_in[4];
    float* out = (float*)d_out;

    dim3 grid(CHUNKS, B_);
    ffl_fused_kernel<<<grid, THREADS>>>(feat, feat_p, avg_feat, qual, label, out);
}